// round 8
// baseline (speedup 1.0000x reference)
#include <cuda_runtime.h>
#include <cuda_fp16.h>
#include <math.h>
#include <stdint.h>

#define NN 8192
#define FD 128
#define HEPS 1e-7f
#define MAXT (1.0f - 1e-6f)
#define PA 132    // A/C smem row pad
#define PB 136    // B smem row pad
#define PA2 260   // gemm2 A row pad

// Scratch (no allocations allowed) — fp16 intermediates
__device__ __half g_Vh[NN * FD];       // V (feeds spmm gather only)
__device__ __half g_Wh[NN * 2 * FD];   // W (feeds gemm2, converted to tf32 there)

__device__ __forceinline__ float wsum(float v) {
#pragma unroll
    for (int o = 16; o > 0; o >>= 1) v += __shfl_xor_sync(0xffffffffu, v, o);
    return v;
}

__device__ __forceinline__ uint32_t f2tf(float f) {
    uint32_t u;
    asm("cvt.rna.tf32.f32 %0, %1;" : "=r"(u) : "f"(f));
    return u;
}

__device__ __forceinline__ void mma_tf32(float c[4], uint32_t a0, uint32_t a1,
                                         uint32_t a2, uint32_t a3,
                                         uint32_t b0, uint32_t b1) {
    asm volatile(
        "mma.sync.aligned.m16n8k8.row.col.f32.tf32.tf32.f32 "
        "{%0,%1,%2,%3},{%4,%5,%6,%7},{%8,%9},{%0,%1,%2,%3};"
        : "+f"(c[0]), "+f"(c[1]), "+f"(c[2]), "+f"(c[3])
        : "r"(a0), "r"(a1), "r"(a2), "r"(a3), "r"(b0), "r"(b1));
}

// Mobius epilogue reading staged accumulators from smem; warp owns 8 rows.
// MODE 0: log0(h_add(exp0(T),b)) -> half output; MODE 1: h_add(exp0(T),b) -> float
template <int MODE>
__device__ __forceinline__ void mobius_smem(const float* __restrict__ Cs,
                                            const float* __restrict__ bias,
                                            int br, int wid, int lane,
                                            void* __restrict__ out) {
    float4 bv = ((const float4*)bias)[lane];
    float y2 = wsum(bv.x * bv.x + bv.y * bv.y + bv.z * bv.z + bv.w * bv.w);
#pragma unroll
    for (int r = 0; r < 8; r++) {
        int lrow = wid * 8 + r;
        int row = br + lrow;
        float4 t = ((const float4*)(Cs + lrow * PA))[lane];
        float t0 = t.x, t1 = t.y, t2 = t.z, t3 = t.w;
        float ss  = wsum(t0 * t0 + t1 * t1 + t2 * t2 + t3 * t3);
        float dtb = wsum(t0 * bv.x + t1 * bv.y + t2 * bv.z + t3 * bv.w);
        float n = fmaxf(sqrtf(ss), HEPS);
        float s = tanhf(n) / n;                       // exp0 scale
        float x2 = s * s * ss;
        float xy = s * dtb;
        float cnum = 1.f + 2.f * xy + y2;
        float cx = 1.f - x2;
        float inv = 1.f / fmaxf(1.f + 2.f * xy + x2 * y2, HEPS);
        float o0 = (cnum * s * t0 + cx * bv.x) * inv;
        float o1 = (cnum * s * t1 + cx * bv.y) * inv;
        float o2 = (cnum * s * t2 + cx * bv.z) * inv;
        float o3 = (cnum * s * t3 + cx * bv.w) * inv;
        if (MODE == 0) {
            float sso = wsum(o0 * o0 + o1 * o1 + o2 * o2 + o3 * o3);
            float no = fmaxf(sqrtf(sso), HEPS);
            float so = atanhf(fminf(no, MAXT)) / no;
            o0 *= so; o1 *= so; o2 *= so; o3 *= so;
            __half2 h0 = __floats2half2_rn(o0, o1);
            __half2 h1 = __floats2half2_rn(o2, o3);
            uint2 u = make_uint2(*(uint32_t*)&h0, *(uint32_t*)&h1);
            ((uint2*)((__half*)out + (size_t)row * FD))[lane] = u;
        } else {
            ((float4*)((float*)out + (size_t)row * FD))[lane] =
                make_float4(o0, o1, o2, o3);
        }
    }
}

// ---------------------------------------------------------------------------
// GEMM1 (tf32 mma, BM=64): V = log0(h_add(exp0(log0(x) @ embed), eb)) -> half
// 256 thr; mma warps in 2x4 grid, each warp 32 rows x 32 cols (2 m-frags).
// ---------------------------------------------------------------------------
__global__ __launch_bounds__(256) void k_gemm1(
    const float* __restrict__ X, const float* __restrict__ B,
    const float* __restrict__ bias, __half* __restrict__ out) {
    extern __shared__ char smraw[];
    float*    Asf = (float*)smraw;                       // [64][PA]
    uint32_t* Asu = (uint32_t*)smraw;
    uint32_t* Bsu = (uint32_t*)(smraw + 64 * PA * 4);    // [128][PB]
    float*    Cs  = (float*)smraw;                       // [64][PA] (reuse)
    const int tid = threadIdx.x;
    const int lane = tid & 31;
    const int wid = tid >> 5;
    const int br = blockIdx.x * 64;

    // load A fp32: 64x32 float4 = 2048 / 256 thr = 8 iters
#pragma unroll
    for (int i = 0; i < 8; i++) {
        int idx4 = tid + i * 256;
        int r = idx4 >> 5, c4 = idx4 & 31;
        ((float4*)(Asf + r * PA))[c4] = ((const float4*)(X + (size_t)(br + r) * FD))[c4];
    }
    // load B, cvt -> tf32: 4096 float4 / 256 = 16 iters
#pragma unroll
    for (int i = 0; i < 16; i++) {
        int idx4 = tid + i * 256;
        int k = idx4 >> 5, c4 = idx4 & 31;
        float4 v = ((const float4*)B)[idx4];
        uint4 u = make_uint4(f2tf(v.x), f2tf(v.y), f2tf(v.z), f2tf(v.w));
        ((uint4*)(Bsu + k * PB))[c4] = u;
    }
    __syncthreads();

    // log0 scaling + cvt->tf32 in place: warp wid owns rows wid*8..+7
#pragma unroll
    for (int r = 0; r < 8; r++) {
        int row = wid * 8 + r;
        float4 v = ((float4*)(Asf + row * PA))[lane];
        float ss = wsum(v.x * v.x + v.y * v.y + v.z * v.z + v.w * v.w);
        float n = fmaxf(sqrtf(ss), HEPS);
        float s = atanhf(fminf(n, MAXT)) / n;
        uint4 u = make_uint4(f2tf(v.x * s), f2tf(v.y * s), f2tf(v.z * s), f2tf(v.w * s));
        ((uint4*)(Asu + row * PA))[lane] = u;
    }
    __syncthreads();

    const int qr = lane >> 2, qc = lane & 3;
    const int wm = (wid >> 2) * 32;       // 0 or 32
    const int wn = (wid & 3) * 32;        // 0,32,64,96
    float acc[2][4][4];
#pragma unroll
    for (int mf = 0; mf < 2; mf++)
#pragma unroll
        for (int nt = 0; nt < 4; nt++)
#pragma unroll
            for (int c = 0; c < 4; c++) acc[mf][nt][c] = 0.f;

#pragma unroll
    for (int ks = 0; ks < 16; ks++) {
        int k0 = ks * 8;
        uint32_t af[2][4];
#pragma unroll
        for (int mf = 0; mf < 2; mf++) {
            int m0 = wm + mf * 16;
            af[mf][0] = Asu[(m0 + qr) * PA + k0 + qc];
            af[mf][1] = Asu[(m0 + 8 + qr) * PA + k0 + qc];
            af[mf][2] = Asu[(m0 + qr) * PA + k0 + 4 + qc];
            af[mf][3] = Asu[(m0 + 8 + qr) * PA + k0 + 4 + qc];
        }
#pragma unroll
        for (int nt = 0; nt < 4; nt++) {
            int nb = wn + nt * 8;
            uint32_t b0 = Bsu[(k0 + qc) * PB + nb + qr];
            uint32_t b1 = Bsu[(k0 + 4 + qc) * PB + nb + qr];
#pragma unroll
            for (int mf = 0; mf < 2; mf++)
                mma_tf32(acc[mf][nt], af[mf][0], af[mf][1], af[mf][2], af[mf][3], b0, b1);
        }
    }
    __syncthreads();   // all mma A-reads done before C overwrites region

#pragma unroll
    for (int mf = 0; mf < 2; mf++)
#pragma unroll
        for (int nt = 0; nt < 4; nt++) {
            int m0 = wm + mf * 16;
            int col = wn + nt * 8 + 2 * qc;
            *(float2*)&Cs[(m0 + qr) * PA + col]     = make_float2(acc[mf][nt][0], acc[mf][nt][1]);
            *(float2*)&Cs[(m0 + 8 + qr) * PA + col] = make_float2(acc[mf][nt][2], acc[mf][nt][3]);
        }
    __syncthreads();

    mobius_smem<0>(Cs, bias, br, wid, lane, out);
}

// ---------------------------------------------------------------------------
// GEMM2 (tf32 mma, BM=64): out = h_add(exp0(W @ layer), lb). W is half.
// ---------------------------------------------------------------------------
__global__ __launch_bounds__(256) void k_gemm2(
    const __half* __restrict__ A, const float* __restrict__ B,
    const float* __restrict__ bias, float* __restrict__ out) {
    extern __shared__ char smraw[];
    uint32_t* Asu = (uint32_t*)smraw;                     // [64][PA2]
    uint32_t* Bsu = (uint32_t*)(smraw + 64 * PA2 * 4);    // [128][PB]
    float*    Cs  = (float*)smraw;                        // [64][PA] (reuse)
    const int tid = threadIdx.x;
    const int lane = tid & 31;
    const int wid = tid >> 5;
    const int br = blockIdx.x * 64;

    // load A (64 x 256 half) -> tf32: 2048 uint4 (8 halves each) / 256 = 8 iters
#pragma unroll
    for (int i = 0; i < 8; i++) {
        int idx8 = tid + i * 256;
        int r = idx8 >> 5, c8 = idx8 & 31;   // 32 groups of 8 halves per row
        uint4 raw = ((const uint4*)(A + (size_t)(br + r) * (2 * FD)))[c8];
        const __half2* hp = (const __half2*)&raw;
        uint32_t* dst = Asu + r * PA2 + c8 * 8;
#pragma unroll
        for (int j = 0; j < 4; j++) {
            float2 f = __half22float2(hp[j]);
            dst[2 * j]     = f2tf(f.x);
            dst[2 * j + 1] = f2tf(f.y);
        }
    }

    const int qr = lane >> 2, qc = lane & 3;
    const int wm = (wid >> 2) * 32;
    const int wn = (wid & 3) * 32;
    float acc[2][4][4];
#pragma unroll
    for (int mf = 0; mf < 2; mf++)
#pragma unroll
        for (int nt = 0; nt < 4; nt++)
#pragma unroll
            for (int c = 0; c < 4; c++) acc[mf][nt][c] = 0.f;

#pragma unroll
    for (int chunk = 0; chunk < 2; chunk++) {
        __syncthreads();
#pragma unroll
        for (int i = 0; i < 16; i++) {
            int idx4 = tid + i * 256;
            int k = idx4 >> 5, c4 = idx4 & 31;
            float4 v = ((const float4*)(B + (size_t)chunk * FD * FD))[idx4];
            uint4 u = make_uint4(f2tf(v.x), f2tf(v.y), f2tf(v.z), f2tf(v.w));
            ((uint4*)(Bsu + k * PB))[c4] = u;
        }
        __syncthreads();
#pragma unroll
        for (int ks = 0; ks < 16; ks++) {
            int k0 = ks * 8;
            int ka = chunk * FD + k0;
            uint32_t af[2][4];
#pragma unroll
            for (int mf = 0; mf < 2; mf++) {
                int m0 = wm + mf * 16;
                af[mf][0] = Asu[(m0 + qr) * PA2 + ka + qc];
                af[mf][1] = Asu[(m0 + 8 + qr) * PA2 + ka + qc];
                af[mf][2] = Asu[(m0 + qr) * PA2 + ka + 4 + qc];
                af[mf][3] = Asu[(m0 + 8 + qr) * PA2 + ka + 4 + qc];
            }
#pragma unroll
            for (int nt = 0; nt < 4; nt++) {
                int nb = wn + nt * 8;
                uint32_t b0 = Bsu[(k0 + qc) * PB + nb + qr];
                uint32_t b1 = Bsu[(k0 + 4 + qc) * PB + nb + qr];
#pragma unroll
                for (int mf = 0; mf < 2; mf++)
                    mma_tf32(acc[mf][nt], af[mf][0], af[mf][1], af[mf][2], af[mf][3], b0, b1);
            }
        }
    }
    __syncthreads();

#pragma unroll
    for (int mf = 0; mf < 2; mf++)
#pragma unroll
        for (int nt = 0; nt < 4; nt++) {
            int m0 = wm + mf * 16;
            int col = wn + nt * 8 + 2 * qc;
            *(float2*)&Cs[(m0 + qr) * PA + col]     = make_float2(acc[mf][nt][0], acc[mf][nt][1]);
            *(float2*)&Cs[(m0 + 8 + qr) * PA + col] = make_float2(acc[mf][nt][2], acc[mf][nt][3]);
        }
    __syncthreads();

    mobius_smem<1>(Cs, bias, br, wid, lane, out);
}

// ---------------------------------------------------------------------------
// SpMM + concat/log fusion: W = log0(concat(x, exp0(adj @ V))), V/W in half.
// One warp per row, scalar-ballot inner loop, one-chunk prefetch.
// Gather reads 8B/lane (4 halves) -> halves L2 gather traffic.
// ---------------------------------------------------------------------------
__global__ __launch_bounds__(256) void k_spmm_fused(
    const float* __restrict__ adj, const __half* __restrict__ V,
    const float* __restrict__ x, __half* __restrict__ W) {
    int row = (blockIdx.x * blockDim.x + threadIdx.x) >> 5;
    int lane = threadIdx.x & 31;
    if (row >= NN) return;
    const float* arow = adj + (size_t)row * NN;
    float ax = 0.f, ay = 0.f, az = 0.f, aw = 0.f;

    float cur[4];
#pragma unroll
    for (int q = 0; q < 4; q++) cur[q] = arow[q * 32 + lane];

    for (int base = 0; base < NN; base += 128) {
        float nxt[4] = {0.f, 0.f, 0.f, 0.f};
        int nb = base + 128;
        if (nb < NN) {
#pragma unroll
            for (int q = 0; q < 4; q++) nxt[q] = arow[nb + q * 32 + lane];
        }
#pragma unroll
        for (int q = 0; q < 4; q++) {
            unsigned m = __ballot_sync(0xffffffffu, cur[q] != 0.f);
            while (m) {
                int src = __ffs(m) - 1;
                m &= m - 1;
                float aj = __shfl_sync(0xffffffffu, cur[q], src);
                uint2 raw = ((const uint2*)(V + (size_t)(base + q * 32 + src) * FD))[lane];
                float2 v01 = __half22float2(*(const __half2*)&raw.x);
                float2 v23 = __half22float2(*(const __half2*)&raw.y);
                ax += aj * v01.x; ay += aj * v01.y;
                az += aj * v23.x; aw += aj * v23.y;
            }
        }
#pragma unroll
        for (int q = 0; q < 4; q++) cur[q] = nxt[q];
    }

    // fused epilogue: W = log0(concat(x, exp0(AV))), written as half
    float ssa = wsum(ax * ax + ay * ay + az * az + aw * aw);
    float na = fmaxf(sqrtf(ssa), HEPS);
    float sa = tanhf(na) / na;
    float4 xv = ((const float4*)(x + (size_t)row * FD))[lane];
    float ssx = wsum(xv.x * xv.x + xv.y * xv.y + xv.z * xv.z + xv.w * xv.w);
    float tot = ssx + sa * sa * ssa;
    float n = fmaxf(sqrtf(tot), HEPS);
    float s = atanhf(fminf(n, MAXT)) / n;
    __half* wr = W + (size_t)row * 2 * FD;
    {
        __half2 h0 = __floats2half2_rn(s * xv.x, s * xv.y);
        __half2 h1 = __floats2half2_rn(s * xv.z, s * xv.w);
        ((uint2*)wr)[lane] = make_uint2(*(uint32_t*)&h0, *(uint32_t*)&h1);
    }
    {
        float sb = s * sa;
        __half2 h0 = __floats2half2_rn(sb * ax, sb * ay);
        __half2 h1 = __floats2half2_rn(sb * az, sb * aw);
        ((uint2*)(wr + FD))[lane] = make_uint2(*(uint32_t*)&h0, *(uint32_t*)&h1);
    }
}

// ---------------------------------------------------------------------------
extern "C" void kernel_launch(void* const* d_in, const int* in_sizes, int n_in,
                              void* d_out, int out_size) {
    const float* x     = (const float*)d_in[0];
    const float* adj   = (const float*)d_in[1];
    const float* embed = (const float*)d_in[2];
    const float* layer = (const float*)d_in[3];
    const float* eb    = (const float*)d_in[4];
    const float* lb    = (const float*)d_in[5];
    float* out = (float*)d_out;
    (void)in_sizes; (void)n_in; (void)out_size;

    __half *pV, *pW;
    cudaGetSymbolAddress((void**)&pV, g_Vh);
    cudaGetSymbolAddress((void**)&pW, g_Wh);

    const int smem1 = (64 * PA + 128 * PB) * 4;   // ~103.4 KB
    const int smem2 = (64 * PA2 + 128 * PB) * 4;  // ~136.2 KB
    cudaFuncSetAttribute(k_gemm1, cudaFuncAttributeMaxDynamicSharedMemorySize, smem1);
    cudaFuncSetAttribute(k_gemm2, cudaFuncAttributeMaxDynamicSharedMemorySize, smem2);

    // 1. V = log0(h_add(exp0(log0(x) @ embed), eb))  [half]
    k_gemm1<<<NN / 64, 256, smem1>>>(x, embed, eb, pV);
    // 2. W = log0(concat(x, exp0(adj @ V)))          [half]
    k_spmm_fused<<<NN / 8, 256>>>(adj, pV, x, pW);
    // 3. out = h_add(exp0(W @ layer), lb)            [float]
    k_gemm2<<<NN / 64, 256, smem2>>>(pW, layer, lb, out);
}